// round 11
// baseline (speedup 1.0000x reference)
#include <cuda_runtime.h>
#include <cuda_fp16.h>

#define N_CUST 100000
#define N_PROD 10000
#define NREL 5
#define SEG 128                 // fixed CSR segment stride (max degree ~80, 11 sigma margin)
#define ROWDOT_BLOCKS 13750     // (N_CUST+N_PROD) warps / 8
#define SCAT_BLOCKS_PER 320
#define PHASE1_EDGE_BLOCKS (SCAT_BLOCKS_PER * 5)
#define A2PAD 40                // halves per smem row, A tile (80B stride, conflict-free)
#define B2PAD 136               // halves per smem row, B/Rs tiles (272B stride)
#define WPAD 72                 // halves per smem row, Wout tile (144B stride)

// ------------------------- device scratch (no allocs allowed) -------------------------
// NOTE: zero-init invariant — g_cnt is re-zeroed by agg_all after use; g_deg_s by
// gemm_tc. Initial state comes from module-load zero init. No zeroing pass needed.
__device__ float  g_wsvec[128];           // Ws_gat @ a_s
__device__ float  g_wdvec[128];           // Wd_gat @ a_d
__device__ float  g_bias[128];            // sum of 5 branch biases
__device__ float  g_ls[N_CUST];
__device__ float  g_ld[N_PROD];
__device__ int    g_deg_s[N_CUST];        // purchase src degree
__device__ int    g_cnt[NREL][N_PROD];    // cursor during scatter == degree after
__device__ int    g_sorted[NREL][N_PROD * SEG];
__device__ uint2  g_xch[N_CUST * 32];     // x_cust rows as fp16 (32 x 8B per row)
__device__ uint2  g_xph[N_PROD * 32];     // x_prod rows as fp16
__device__ uint2  g_feath[NREL][N_PROD * 32];  // aggregated features, fp16
__device__ __half g_wh[6][128 * 128];     // fp16 weights: Wg,Wsg,Wlt,Wlf,Wld,wrsum
__device__ __half g_wouth[128 * 64];      // fp16 W_out

struct EdgePtrs {
    const int* src[NREL];
    const int* dst[NREL];
    int E;
};

// ------------------------- tensor-core helpers -------------------------
__device__ __forceinline__ unsigned smem_u32(const void* p) {
    return (unsigned)__cvta_generic_to_shared(p);
}
__device__ __forceinline__ void ldsm_x4(unsigned& r0, unsigned& r1, unsigned& r2, unsigned& r3,
                                        unsigned addr) {
    asm volatile("ldmatrix.sync.aligned.m8n8.x4.shared.b16 {%0,%1,%2,%3}, [%4];"
                 : "=r"(r0), "=r"(r1), "=r"(r2), "=r"(r3) : "r"(addr));
}
__device__ __forceinline__ void ldsm_x4t(unsigned& r0, unsigned& r1, unsigned& r2, unsigned& r3,
                                         unsigned addr) {
    asm volatile("ldmatrix.sync.aligned.m8n8.x4.trans.shared.b16 {%0,%1,%2,%3}, [%4];"
                 : "=r"(r0), "=r"(r1), "=r"(r2), "=r"(r3) : "r"(addr));
}
__device__ __forceinline__ void mma16816(float* d, const unsigned* a, const unsigned* b) {
    asm volatile(
        "mma.sync.aligned.m16n8k16.row.col.f32.f16.f16.f32 "
        "{%0,%1,%2,%3},{%4,%5,%6,%7},{%8,%9},{%0,%1,%2,%3};"
        : "+f"(d[0]), "+f"(d[1]), "+f"(d[2]), "+f"(d[3])
        : "r"(a[0]), "r"(a[1]), "r"(a[2]), "r"(a[3]), "r"(b[0]), "r"(b[1]));
}

// ------------------------- setup: weight prep only (105 small blocks) ------------------
__global__ void setup_kernel(const float* __restrict__ Ws, const float* __restrict__ Wd,
                             const float* __restrict__ a_s, const float* __restrict__ a_d,
                             const float* __restrict__ bg, const float* __restrict__ bgat,
                             const float* __restrict__ bto, const float* __restrict__ bfrom,
                             const float* __restrict__ bdiv,
                             const float* __restrict__ Wg, const float* __restrict__ Wlt,
                             const float* __restrict__ Wlf, const float* __restrict__ Wld,
                             const float* __restrict__ Wrt, const float* __restrict__ Wrf,
                             const float* __restrict__ Wrd, const float* __restrict__ Wout) {
    int b = blockIdx.x;
    int tid = threadIdx.x;
    if (b == 0) {
        if (tid < 128) {
            float s1 = 0.f, s2 = 0.f;
            for (int j = 0; j < 128; j++) {
                s1 += Ws[tid * 128 + j] * a_s[j];
                s2 += Wd[tid * 128 + j] * a_d[j];
            }
            g_wsvec[tid] = s1;
            g_wdvec[tid] = s2;
            g_bias[tid] = bg[tid] + bgat[tid] + bto[tid] + bfrom[tid] + bdiv[tid];
        }
    } else if (b <= 96) {
        int p = (b - 1) >> 4;
        int idx = ((b - 1) & 15) * 1024 + tid * 4;
        const float* srcs[5] = {Wg, Ws, Wlt, Wlf, Wld};
        float4 v;
        if (p < 5) v = *(const float4*)&srcs[p][idx];
        else {
            float4 v0 = *(const float4*)&Wrt[idx];
            float4 v1 = *(const float4*)&Wrf[idx];
            float4 v2 = *(const float4*)&Wrd[idx];
            v = make_float4(v0.x + v1.x + v2.x, v0.y + v1.y + v2.y,
                            v0.z + v1.z + v2.z, v0.w + v1.w + v2.w);
        }
        __half2 h0 = __floats2half2_rn(v.x, v.y);
        __half2 h1 = __floats2half2_rn(v.z, v.w);
        uint2 u;
        u.x = *reinterpret_cast<unsigned*>(&h0);
        u.y = *reinterpret_cast<unsigned*>(&h1);
        *(uint2*)&g_wh[p][idx] = u;
    } else {
        int idx = (b - 97) * 1024 + tid * 4;
        float4 v = *(const float4*)&Wout[idx];
        __half2 h0 = __floats2half2_rn(v.x, v.y);
        __half2 h1 = __floats2half2_rn(v.z, v.w);
        uint2 u;
        u.x = *reinterpret_cast<unsigned*>(&h0);
        u.y = *reinterpret_cast<unsigned*>(&h1);
        *(uint2*)&g_wouth[idx] = u;
    }
}

// ---- phase1: fused {5x direct scatter (slice 0 also builds deg_s), rowdot/convert} ---
__global__ void phase1_kernel(const float* __restrict__ xc, const float* __restrict__ xp,
                              EdgePtrs ep) {
    int b = blockIdx.x;
    if (b < PHASE1_EDGE_BLOCKS) {
        int slice = b / SCAT_BLOCKS_PER;   // relation 0..4
        int bx = b % SCAT_BLOCKS_PER;
        const int* src = ep.src[slice];
        const int* dst = ep.dst[slice];
        int* cnt = g_cnt[slice];
        int* srt = g_sorted[slice];
        if (slice == 0) {
            for (int i = bx * 256 + (int)threadIdx.x; i < ep.E; i += SCAT_BLOCKS_PER * 256) {
                int s = src[i];
                int d = dst[i];
                atomicAdd(&g_deg_s[s], 1);
                int p = atomicAdd(&cnt[d], 1);
                if (p < SEG) srt[(d << 7) + p] = s;
            }
        } else {
            for (int i = bx * 256 + (int)threadIdx.x; i < ep.E; i += SCAT_BLOCKS_PER * 256) {
                int d = dst[i];
                int p = atomicAdd(&cnt[d], 1);
                if (p < SEG) srt[(d << 7) + p] = src[i];
            }
        }
    } else {
        int b2 = b - PHASE1_EDGE_BLOCKS;
        int gw = (b2 * 256 + (int)threadIdx.x) >> 5;
        int lane = threadIdx.x & 31;
        float4 wv, xv;
        if (gw < N_CUST) {
            wv = ((const float4*)g_wsvec)[lane];
            xv = ((const float4*)xc)[gw * 32 + lane];
        } else {
            wv = ((const float4*)g_wdvec)[lane];
            xv = ((const float4*)xp)[(gw - N_CUST) * 32 + lane];
        }
        __half2 h0 = __floats2half2_rn(xv.x, xv.y);
        __half2 h1 = __floats2half2_rn(xv.z, xv.w);
        uint2 u;
        u.x = *reinterpret_cast<unsigned*>(&h0);
        u.y = *reinterpret_cast<unsigned*>(&h1);
        if (gw < N_CUST) g_xch[gw * 32 + lane] = u;
        else g_xph[(gw - N_CUST) * 32 + lane] = u;
        float d = xv.x * wv.x + xv.y * wv.y + xv.z * wv.z + xv.w * wv.w;
#pragma unroll
        for (int o = 16; o; o >>= 1) d += __shfl_xor_sync(0xffffffffu, d, o);
        if (lane == 0) {
            if (gw < N_CUST) g_ls[gw] = d; else g_ld[gw - N_CUST] = d;
        }
    }
}

// ------------------------- fp16 gather helper (uint4 = 8 halves) ----------------------
__device__ __forceinline__ void acc_h4(float4& a0, float4& a1, uint4 u, float w) {
    __half2* h = reinterpret_cast<__half2*>(&u);
    float2 f0 = __half22float2(h[0]);
    float2 f1 = __half22float2(h[1]);
    float2 f2 = __half22float2(h[2]);
    float2 f3 = __half22float2(h[3]);
    a0.x += w * f0.x; a0.y += w * f0.y; a0.z += w * f1.x; a0.w += w * f1.y;
    a1.x += w * f2.x; a1.y += w * f2.y; a1.z += w * f3.x; a1.w += w * f3.y;
}

// ------------------------- all 5 aggregations: warp = dst row, 4 edges in flight ------
// 16 lanes cover the 256B fp16 row (uint4 each); half = lane>>4 picks edge parity.
__global__ void agg_all() {
    int gw = (blockIdx.x * blockDim.x + threadIdx.x) >> 5;
    if (gw >= N_PROD) return;
    int lane = threadIdx.x & 31;
    int half = lane >> 4;       // edge parity
    int q = lane & 15;          // 16B chunk within row
    int rel = blockIdx.y;
    int c = g_cnt[rel][gw];
    if (lane == 0) g_cnt[rel][gw] = 0;   // restore zero-invariant for next replay
    if (c > SEG) c = SEG;
    const int* srt = &g_sorted[rel][gw << 7];
    const uint4* xh4 = (const uint4*)g_xch;
    float4 a0 = make_float4(0.f, 0.f, 0.f, 0.f);
    float4 a1 = make_float4(0.f, 0.f, 0.f, 0.f);
    float den = 0.f;
    float ldv = (rel == 1) ? g_ld[gw] : 0.f;

    int e = half;
    for (; e + 6 < c; e += 8) {
        int s0 = srt[e], s1 = srt[e + 2], s2 = srt[e + 4], s3 = srt[e + 6];
        float w0, w1, w2, w3;
        if (rel >= 2) { w0 = w1 = w2 = w3 = 1.f; }
        else if (rel == 0) {
            w0 = rsqrtf((float)g_deg_s[s0]);
            w1 = rsqrtf((float)g_deg_s[s1]);
            w2 = rsqrtf((float)g_deg_s[s2]);
            w3 = rsqrtf((float)g_deg_s[s3]);
        } else {
            float l0 = g_ls[s0] + ldv;
            float l1 = g_ls[s1] + ldv;
            float l2 = g_ls[s2] + ldv;
            float l3 = g_ls[s3] + ldv;
            l0 = (l0 > 0.f) ? l0 : 0.2f * l0;
            l1 = (l1 > 0.f) ? l1 : 0.2f * l1;
            l2 = (l2 > 0.f) ? l2 : 0.2f * l2;
            l3 = (l3 > 0.f) ? l3 : 0.2f * l3;
            w0 = __expf(l0); w1 = __expf(l1); w2 = __expf(l2); w3 = __expf(l3);
            den += (w0 + w1) + (w2 + w3);
        }
        uint4 u0 = xh4[s0 * 16 + q];
        uint4 u1 = xh4[s1 * 16 + q];
        uint4 u2 = xh4[s2 * 16 + q];
        uint4 u3 = xh4[s3 * 16 + q];
        acc_h4(a0, a1, u0, w0);
        acc_h4(a0, a1, u1, w1);
        acc_h4(a0, a1, u2, w2);
        acc_h4(a0, a1, u3, w3);
    }
    for (; e < c; e += 2) {
        int s0 = srt[e];
        float w0;
        if (rel >= 2) w0 = 1.f;
        else if (rel == 0) w0 = rsqrtf((float)g_deg_s[s0]);
        else {
            float l0 = g_ls[s0] + ldv;
            l0 = (l0 > 0.f) ? l0 : 0.2f * l0;
            w0 = __expf(l0);
            den += w0;
        }
        uint4 u0 = xh4[s0 * 16 + q];
        acc_h4(a0, a1, u0, w0);
    }

    // combine the two edge-parity halves
    a0.x += __shfl_xor_sync(0xffffffffu, a0.x, 16);
    a0.y += __shfl_xor_sync(0xffffffffu, a0.y, 16);
    a0.z += __shfl_xor_sync(0xffffffffu, a0.z, 16);
    a0.w += __shfl_xor_sync(0xffffffffu, a0.w, 16);
    a1.x += __shfl_xor_sync(0xffffffffu, a1.x, 16);
    a1.y += __shfl_xor_sync(0xffffffffu, a1.y, 16);
    a1.z += __shfl_xor_sync(0xffffffffu, a1.z, 16);
    a1.w += __shfl_xor_sync(0xffffffffu, a1.w, 16);
    if (rel == 1) den += __shfl_xor_sync(0xffffffffu, den, 16);

    float sc;
    if (rel >= 2) sc = 1.0f / (float)(c < 1 ? 1 : c);
    else if (rel == 0) sc = (c > 0) ? rsqrtf((float)c) : 0.f;
    else sc = (c > 0) ? (1.0f / den) : 0.f;
    a0.x *= sc; a0.y *= sc; a0.z *= sc; a0.w *= sc;
    a1.x *= sc; a1.y *= sc; a1.z *= sc; a1.w *= sc;

    if (half == 0) {
        uint4 u;
        __half2 h;
        h = __floats2half2_rn(a0.x, a0.y); u.x = *reinterpret_cast<unsigned*>(&h);
        h = __floats2half2_rn(a0.z, a0.w); u.y = *reinterpret_cast<unsigned*>(&h);
        h = __floats2half2_rn(a1.x, a1.y); u.z = *reinterpret_cast<unsigned*>(&h);
        h = __floats2half2_rn(a1.z, a1.w); u.w = *reinterpret_cast<unsigned*>(&h);
        ((uint4*)g_feath[rel])[gw * 16 + q] = u;
    }
}

// ------------- fused tensor-core GEMM, double-buffered stage A --------------------------
// BM=32, 256 threads (8 warps: 2 m-warps x 4 n-warps), grid 313 (2 blocks/SM).
// Stage A: 24 chunks of K=32 (6 sources x 4 quarters), 2-buffer smem, 1 barrier/chunk.
// Stage B: fp16 Rs @ Wout. Also restores g_deg_s zero-invariant.
// smem: stage A = 2*(32*40 + 32*136)*2 = 22528 B; stage B = 32*136*2 + 128*72*2 = 27136 B.
__global__ void __launch_bounds__(256) gemm_tc(const float* __restrict__ bout,
                                               float* __restrict__ out) {
    __shared__ __align__(16) char sbuf[27136];
    typedef __half (*A2t)[A2PAD];
    typedef __half (*B2t)[B2PAD];
    A2t As2[2] = {(A2t)sbuf, (A2t)(sbuf + 2560)};
    B2t Bs2[2] = {(B2t)(sbuf + 5120), (B2t)(sbuf + 13824)};
    __half (*Rs)[B2PAD] = (__half (*)[B2PAD])sbuf;                 // stage B alias
    __half (*Ws2)[WPAD] = (__half (*)[WPAD])(sbuf + 8704);         // stage B alias

    int tid = threadIdx.x;
    int wid = tid >> 5, lane = tid & 31;
    int warp_m = wid & 1, warp_n = wid >> 1;   // 2 x 4
    int m0 = blockIdx.x * 32;
    int lrow = lane & 15, lcol = (lane >> 4) << 3;

    // restore deg_s zero-invariant (independent of this kernel's compute)
    for (int i = blockIdx.x * 256 + tid; i < N_CUST; i += gridDim.x * 256)
        g_deg_s[i] = 0;

    // per-thread load coordinates
    int am = tid >> 2, acA = tid & 3;          // A: threads 0..127 load row am, uint4 acA
    bool aldr = (tid < 128);
    int arow = m0 + am;

    float acc[4][4];
#pragma unroll
    for (int f = 0; f < 4; f++)
#pragma unroll
        for (int i = 0; i < 4; i++) acc[f][i] = 0.f;

    const uint4* Asrc[6] = {(const uint4*)g_feath[0], (const uint4*)g_feath[1],
                            (const uint4*)g_feath[2], (const uint4*)g_feath[3],
                            (const uint4*)g_feath[4], (const uint4*)g_xph};

    uint4 ra = make_uint4(0u, 0u, 0u, 0u);
    uint4 rb[2];

    // prologue: chunk 0 (p=0,q=0)
    if (aldr && arow < N_PROD) ra = Asrc[0][arow * 16 + acA];
    {
        const uint4* Bp = (const uint4*)g_wh[0];
#pragma unroll
        for (int t = 0; t < 2; t++) {
            int idx = tid + t * 256;
            int k = idx >> 4, cc = idx & 15;
            rb[t] = Bp[k * 16 + cc];
        }
    }
    if (aldr) *(uint4*)&As2[0][am][acA * 8] = ra;
#pragma unroll
    for (int t = 0; t < 2; t++) {
        int idx = tid + t * 256;
        int k = idx >> 4, cc = idx & 15;
        *(uint4*)&Bs2[0][k][cc * 8] = rb[t];
    }

    for (int c = 0; c < 24; c++) {
        int buf = c & 1;
        // prefetch chunk c+1 into registers (overlaps barrier wait + compute)
        if (c < 23) {
            int cn = c + 1;
            int pn = cn >> 2, qn = cn & 3;
            ra = make_uint4(0u, 0u, 0u, 0u);
            if (aldr && arow < N_PROD) ra = Asrc[pn][arow * 16 + qn * 4 + acA];
            const uint4* Bp = (const uint4*)g_wh[pn];
#pragma unroll
            for (int t = 0; t < 2; t++) {
                int idx = tid + t * 256;
                int k = idx >> 4, cc = idx & 15;
                rb[t] = Bp[(qn * 32 + k) * 16 + cc];
            }
        }
        __syncthreads();   // buf[c&1] tiles visible; all warps done with chunk c-1
        // compute chunk c (K=32 -> 2 k-steps)
#pragma unroll
        for (int ks = 0; ks < 2; ks++) {
            int k0 = ks * 16;
            unsigned a[4];
            ldsm_x4(a[0], a[1], a[2], a[3],
                    smem_u32(&As2[buf][warp_m * 16 + lrow][k0 + lcol]));
#pragma unroll
            for (int j = 0; j < 2; j++) {
                unsigned bfrag[4];
                int nb = warp_n * 32 + j * 16;
                ldsm_x4t(bfrag[0], bfrag[1], bfrag[2], bfrag[3],
                         smem_u32(&Bs2[buf][k0 + lrow][nb + lcol]));
                mma16816(acc[j * 2], a, bfrag);
                mma16816(acc[j * 2 + 1], a, bfrag + 2);
            }
        }
        // commit prefetched chunk into the other buffer
        if (c < 23) {
            if (aldr) *(uint4*)&As2[buf ^ 1][am][acA * 8] = ra;
#pragma unroll
            for (int t = 0; t < 2; t++) {
                int idx = tid + t * 256;
                int k = idx >> 4, cc = idx & 15;
                *(uint4*)&Bs2[buf ^ 1][k][cc * 8] = rb[t];
            }
        }
    }
    __syncthreads();   // all compute done before stage-B aliasing writes

    // bias + relu -> Rs (fp16), load Wout -> Ws2
    {
        int r0 = warp_m * 16 + (lane >> 2);
#pragma unroll
        for (int f = 0; f < 4; f++) {
            int cc = warp_n * 32 + (f >> 1) * 16 + (f & 1) * 8 + (lane & 3) * 2;
            float2 bb = *(const float2*)&g_bias[cc];
            float v0 = acc[f][0] + bb.x; v0 = (v0 > 0.f) ? v0 : 0.f;
            float v1 = acc[f][1] + bb.y; v1 = (v1 > 0.f) ? v1 : 0.f;
            float v2 = acc[f][2] + bb.x; v2 = (v2 > 0.f) ? v2 : 0.f;
            float v3 = acc[f][3] + bb.y; v3 = (v3 > 0.f) ? v3 : 0.f;
            *(__half2*)&Rs[r0][cc] = __floats2half2_rn(v0, v1);
            *(__half2*)&Rs[r0 + 8][cc] = __floats2half2_rn(v2, v3);
        }
        const uint4* Wp = (const uint4*)g_wouth;
#pragma unroll
        for (int t = 0; t < 4; t++) {
            int idx = tid + t * 256;
            int k = idx >> 3, cc = idx & 7;
            *(uint4*)&Ws2[k][cc * 8] = Wp[k * 8 + cc];
        }
    }
    __syncthreads();

    float acc2[2][4];
#pragma unroll
    for (int f = 0; f < 2; f++)
#pragma unroll
        for (int i = 0; i < 4; i++) acc2[f][i] = 0.f;

#pragma unroll
    for (int ks = 0; ks < 8; ks++) {
        int k0 = ks * 16;
        unsigned a[4];
        ldsm_x4(a[0], a[1], a[2], a[3],
                smem_u32(&Rs[warp_m * 16 + lrow][k0 + lcol]));
        unsigned bfrag[4];
        int nb = warp_n * 16;
        ldsm_x4t(bfrag[0], bfrag[1], bfrag[2], bfrag[3],
                 smem_u32(&Ws2[k0 + lrow][nb + lcol]));
        mma16816(acc2[0], a, bfrag);
        mma16816(acc2[1], a, bfrag + 2);
    }

    // epilogue: + bout, store f32
    {
        int r = warp_m * 16 + (lane >> 2);
#pragma unroll
        for (int f = 0; f < 2; f++) {
            int cc = warp_n * 16 + f * 8 + (lane & 3) * 2;
            float2 bb = *(const float2*)&bout[cc];
            int row0 = m0 + r;
            int row1 = row0 + 8;
            if (row0 < N_PROD) {
                float2 v = make_float2(acc2[f][0] + bb.x, acc2[f][1] + bb.y);
                *(float2*)&out[row0 * 64 + cc] = v;
            }
            if (row1 < N_PROD) {
                float2 v = make_float2(acc2[f][2] + bb.x, acc2[f][3] + bb.y);
                *(float2*)&out[row1 * 64 + cc] = v;
            }
        }
    }
}

// ------------------------- launch -------------------------
extern "C" void kernel_launch(void* const* d_in, const int* in_sizes, int n_in,
                              void* d_out, int out_size) {
    const float* x_cust = (const float*)d_in[0];
    const float* x_prod = (const float*)d_in[1];
    EdgePtrs ep;
    for (int r = 0; r < NREL; r++) {
        ep.src[r] = (const int*)d_in[2 + 2 * r];
        ep.dst[r] = (const int*)d_in[3 + 2 * r];
    }
    ep.E = in_sizes[2];
    const float* W_gcn  = (const float*)d_in[12];
    const float* b_gcn  = (const float*)d_in[13];
    const float* Ws_gat = (const float*)d_in[14];
    const float* Wd_gat = (const float*)d_in[15];
    const float* a_s    = (const float*)d_in[16];
    const float* a_d    = (const float*)d_in[17];
    const float* b_gat  = (const float*)d_in[18];
    const float* Wl_to  = (const float*)d_in[19];
    const float* b_to   = (const float*)d_in[20];
    const float* Wr_to  = (const float*)d_in[21];
    const float* Wl_fr  = (const float*)d_in[22];
    const float* b_fr   = (const float*)d_in[23];
    const float* Wr_fr  = (const float*)d_in[24];
    const float* Wl_dv  = (const float*)d_in[25];
    const float* b_dv   = (const float*)d_in[26];
    const float* Wr_dv  = (const float*)d_in[27];
    const float* W_out  = (const float*)d_in[28];
    const float* b_out  = (const float*)d_in[29];

    setup_kernel<<<105, 256>>>(Ws_gat, Wd_gat, a_s, a_d,
                               b_gcn, b_gat, b_to, b_fr, b_dv,
                               W_gcn, Wl_to, Wl_fr, Wl_dv,
                               Wr_to, Wr_fr, Wr_dv, W_out);
    phase1_kernel<<<PHASE1_EDGE_BLOCKS + ROWDOT_BLOCKS, 256>>>(x_cust, x_prod, ep);

    dim3 agrid((N_PROD + 7) / 8, 5);
    agg_all<<<agrid, 256>>>();

    gemm_tc<<<(N_PROD + 31) / 32, 256>>>(b_out, (float*)d_out);
}

// round 12
// speedup vs baseline: 1.0129x; 1.0129x over previous
#include <cuda_runtime.h>
#include <cuda_fp16.h>

#define N_CUST 100000
#define N_PROD 10000
#define NREL 5
#define SEG 128                 // fixed CSR segment stride (max degree ~80, 11 sigma margin)
#define ROWDOT_BLOCKS 13750     // (N_CUST+N_PROD) warps / 8
#define SCAT_BLOCKS_PER 160
#define PHASE1_EDGE_BLOCKS (SCAT_BLOCKS_PER * 5)
#define APAD 136                // halves per smem row (272B stride; 272 mod 128 = 16 -> conflict-free)
#define WPAD 72                 // halves per smem row for Wout tile (144B stride)

// ------------------------- device scratch (no allocs allowed) -------------------------
// Zero-invariant: g_cnt cleared by agg_all after use; g_deg_s cleared by gemm_tc.
// Initial state = module-load zero init. No explicit zeroing pass.
__device__ float  g_wsvec[128];           // Ws_gat @ a_s
__device__ float  g_wdvec[128];           // Wd_gat @ a_d
__device__ float  g_bias[128];            // sum of 5 branch biases
__device__ float  g_ls[N_CUST];
__device__ float  g_ld[N_PROD];
__device__ int    g_deg_s[N_CUST];        // purchase src degree
__device__ int    g_cnt[NREL][N_PROD];    // cursor during scatter == degree after
__device__ int    g_sorted[NREL][N_PROD * SEG];
__device__ uint2  g_xch[N_CUST * 32];     // x_cust rows as fp16 (32 x 8B per row)
__device__ uint2  g_xph[N_PROD * 32];     // x_prod rows as fp16
__device__ uint2  g_feath[NREL][N_PROD * 32];  // aggregated features, fp16
__device__ __half g_wh[6][128 * 128];     // fp16 weights: Wg,Wsg,Wlt,Wlf,Wld,wrsum
__device__ __half g_wouth[128 * 64];      // fp16 W_out

struct EdgePtrs {
    const int* src[NREL];
    const int* dst[NREL];
    int E;
};

// ------------------------- tensor-core helpers -------------------------
__device__ __forceinline__ unsigned smem_u32(const void* p) {
    return (unsigned)__cvta_generic_to_shared(p);
}
__device__ __forceinline__ void ldsm_x4(unsigned& r0, unsigned& r1, unsigned& r2, unsigned& r3,
                                        unsigned addr) {
    asm volatile("ldmatrix.sync.aligned.m8n8.x4.shared.b16 {%0,%1,%2,%3}, [%4];"
                 : "=r"(r0), "=r"(r1), "=r"(r2), "=r"(r3) : "r"(addr));
}
__device__ __forceinline__ void ldsm_x4t(unsigned& r0, unsigned& r1, unsigned& r2, unsigned& r3,
                                         unsigned addr) {
    asm volatile("ldmatrix.sync.aligned.m8n8.x4.trans.shared.b16 {%0,%1,%2,%3}, [%4];"
                 : "=r"(r0), "=r"(r1), "=r"(r2), "=r"(r3) : "r"(addr));
}
__device__ __forceinline__ void mma16816(float* d, const unsigned* a, const unsigned* b) {
    asm volatile(
        "mma.sync.aligned.m16n8k16.row.col.f32.f16.f16.f32 "
        "{%0,%1,%2,%3},{%4,%5,%6,%7},{%8,%9},{%0,%1,%2,%3};"
        : "+f"(d[0]), "+f"(d[1]), "+f"(d[2]), "+f"(d[3])
        : "r"(a[0]), "r"(a[1]), "r"(a[2]), "r"(a[3]), "r"(b[0]), "r"(b[1]));
}

// ------------------------- setup: weight prep only (105 small blocks) ------------------
__global__ void setup_kernel(const float* __restrict__ Ws, const float* __restrict__ Wd,
                             const float* __restrict__ a_s, const float* __restrict__ a_d,
                             const float* __restrict__ bg, const float* __restrict__ bgat,
                             const float* __restrict__ bto, const float* __restrict__ bfrom,
                             const float* __restrict__ bdiv,
                             const float* __restrict__ Wg, const float* __restrict__ Wlt,
                             const float* __restrict__ Wlf, const float* __restrict__ Wld,
                             const float* __restrict__ Wrt, const float* __restrict__ Wrf,
                             const float* __restrict__ Wrd, const float* __restrict__ Wout) {
    int b = blockIdx.x;
    int tid = threadIdx.x;
    if (b == 0) {
        if (tid < 128) {
            float s1 = 0.f, s2 = 0.f;
            for (int j = 0; j < 128; j++) {
                s1 += Ws[tid * 128 + j] * a_s[j];
                s2 += Wd[tid * 128 + j] * a_d[j];
            }
            g_wsvec[tid] = s1;
            g_wdvec[tid] = s2;
            g_bias[tid] = bg[tid] + bgat[tid] + bto[tid] + bfrom[tid] + bdiv[tid];
        }
    } else if (b <= 96) {
        int p = (b - 1) >> 4;
        int idx = ((b - 1) & 15) * 1024 + tid * 4;
        const float* srcs[5] = {Wg, Ws, Wlt, Wlf, Wld};
        float4 v;
        if (p < 5) v = *(const float4*)&srcs[p][idx];
        else {
            float4 v0 = *(const float4*)&Wrt[idx];
            float4 v1 = *(const float4*)&Wrf[idx];
            float4 v2 = *(const float4*)&Wrd[idx];
            v = make_float4(v0.x + v1.x + v2.x, v0.y + v1.y + v2.y,
                            v0.z + v1.z + v2.z, v0.w + v1.w + v2.w);
        }
        __half2 h0 = __floats2half2_rn(v.x, v.y);
        __half2 h1 = __floats2half2_rn(v.z, v.w);
        uint2 u;
        u.x = *reinterpret_cast<unsigned*>(&h0);
        u.y = *reinterpret_cast<unsigned*>(&h1);
        *(uint2*)&g_wh[p][idx] = u;
    } else {
        int idx = (b - 97) * 1024 + tid * 4;
        float4 v = *(const float4*)&Wout[idx];
        __half2 h0 = __floats2half2_rn(v.x, v.y);
        __half2 h1 = __floats2half2_rn(v.z, v.w);
        uint2 u;
        u.x = *reinterpret_cast<unsigned*>(&h0);
        u.y = *reinterpret_cast<unsigned*>(&h1);
        *(uint2*)&g_wouth[idx] = u;
    }
}

// ---- phase1: fused {5x direct scatter (slice 0 also builds deg_s), rowdot/convert} ---
__global__ void phase1_kernel(const float* __restrict__ xc, const float* __restrict__ xp,
                              EdgePtrs ep) {
    int b = blockIdx.x;
    if (b < PHASE1_EDGE_BLOCKS) {
        int slice = b / SCAT_BLOCKS_PER;   // relation 0..4
        int bx = b % SCAT_BLOCKS_PER;
        const int* src = ep.src[slice];
        const int* dst = ep.dst[slice];
        int* cnt = g_cnt[slice];
        int* srt = g_sorted[slice];
        if (slice == 0) {
            for (int i = bx * 256 + (int)threadIdx.x; i < ep.E; i += SCAT_BLOCKS_PER * 256) {
                int s = src[i];
                int d = dst[i];
                atomicAdd(&g_deg_s[s], 1);
                int p = atomicAdd(&cnt[d], 1);
                if (p < SEG) srt[(d << 7) + p] = s;
            }
        } else {
            for (int i = bx * 256 + (int)threadIdx.x; i < ep.E; i += SCAT_BLOCKS_PER * 256) {
                int d = dst[i];
                int p = atomicAdd(&cnt[d], 1);
                if (p < SEG) srt[(d << 7) + p] = src[i];
            }
        }
    } else {
        int b2 = b - PHASE1_EDGE_BLOCKS;
        int gw = (b2 * 256 + (int)threadIdx.x) >> 5;
        int lane = threadIdx.x & 31;
        float4 wv, xv;
        if (gw < N_CUST) {
            wv = ((const float4*)g_wsvec)[lane];
            xv = ((const float4*)xc)[gw * 32 + lane];
        } else {
            wv = ((const float4*)g_wdvec)[lane];
            xv = ((const float4*)xp)[(gw - N_CUST) * 32 + lane];
        }
        __half2 h0 = __floats2half2_rn(xv.x, xv.y);
        __half2 h1 = __floats2half2_rn(xv.z, xv.w);
        uint2 u;
        u.x = *reinterpret_cast<unsigned*>(&h0);
        u.y = *reinterpret_cast<unsigned*>(&h1);
        if (gw < N_CUST) g_xch[gw * 32 + lane] = u;
        else g_xph[(gw - N_CUST) * 32 + lane] = u;
        float d = xv.x * wv.x + xv.y * wv.y + xv.z * wv.z + xv.w * wv.w;
#pragma unroll
        for (int o = 16; o; o >>= 1) d += __shfl_xor_sync(0xffffffffu, d, o);
        if (lane == 0) {
            if (gw < N_CUST) g_ls[gw] = d; else g_ld[gw - N_CUST] = d;
        }
    }
}

// ------------------------- fp16 gather helper (uint4 = 8 halves) ----------------------
__device__ __forceinline__ void acc_h4(float4& a0, float4& a1, uint4 u, float w) {
    __half2* h = reinterpret_cast<__half2*>(&u);
    float2 f0 = __half22float2(h[0]);
    float2 f1 = __half22float2(h[1]);
    float2 f2 = __half22float2(h[2]);
    float2 f3 = __half22float2(h[3]);
    a0.x += w * f0.x; a0.y += w * f0.y; a0.z += w * f1.x; a0.w += w * f1.y;
    a1.x += w * f2.x; a1.y += w * f2.y; a1.z += w * f3.x; a1.w += w * f3.y;
}

// ------------------------- all 5 aggregations: warp = dst row, 2 edges in flight ------
// 16 lanes cover the 256B fp16 row (uint4 each); half = lane>>4 picks edge parity.
__global__ void agg_all() {
    int gw = (blockIdx.x * blockDim.x + threadIdx.x) >> 5;
    if (gw >= N_PROD) return;
    int lane = threadIdx.x & 31;
    int half = lane >> 4;       // edge parity
    int q = lane & 15;          // 16B chunk within row
    int rel = blockIdx.y;
    int c = g_cnt[rel][gw];
    if (lane == 0) g_cnt[rel][gw] = 0;   // restore zero-invariant for next replay
    if (c > SEG) c = SEG;
    const int* srt = &g_sorted[rel][gw << 7];
    const uint4* xh4 = (const uint4*)g_xch;
    float4 a0 = make_float4(0.f, 0.f, 0.f, 0.f);
    float4 a1 = make_float4(0.f, 0.f, 0.f, 0.f);
    float den = 0.f;
    float ldv = (rel == 1) ? g_ld[gw] : 0.f;

    int e = half;
    for (; e + 2 < c; e += 4) {
        int s0 = srt[e], s1 = srt[e + 2];
        float w0, w1;
        if (rel >= 2) { w0 = 1.f; w1 = 1.f; }
        else if (rel == 0) {
            w0 = rsqrtf((float)g_deg_s[s0]);
            w1 = rsqrtf((float)g_deg_s[s1]);
        } else {
            float l0 = g_ls[s0] + ldv;
            float l1 = g_ls[s1] + ldv;
            l0 = (l0 > 0.f) ? l0 : 0.2f * l0;
            l1 = (l1 > 0.f) ? l1 : 0.2f * l1;
            w0 = __expf(l0);
            w1 = __expf(l1);
            den += w0 + w1;
        }
        uint4 u0 = xh4[s0 * 16 + q];
        uint4 u1 = xh4[s1 * 16 + q];
        acc_h4(a0, a1, u0, w0);
        acc_h4(a0, a1, u1, w1);
    }
    for (; e < c; e += 2) {
        int s0 = srt[e];
        float w0;
        if (rel >= 2) w0 = 1.f;
        else if (rel == 0) w0 = rsqrtf((float)g_deg_s[s0]);
        else {
            float l0 = g_ls[s0] + ldv;
            l0 = (l0 > 0.f) ? l0 : 0.2f * l0;
            w0 = __expf(l0);
            den += w0;
        }
        uint4 u0 = xh4[s0 * 16 + q];
        acc_h4(a0, a1, u0, w0);
    }

    // combine the two edge-parity halves
    a0.x += __shfl_xor_sync(0xffffffffu, a0.x, 16);
    a0.y += __shfl_xor_sync(0xffffffffu, a0.y, 16);
    a0.z += __shfl_xor_sync(0xffffffffu, a0.z, 16);
    a0.w += __shfl_xor_sync(0xffffffffu, a0.w, 16);
    a1.x += __shfl_xor_sync(0xffffffffu, a1.x, 16);
    a1.y += __shfl_xor_sync(0xffffffffu, a1.y, 16);
    a1.z += __shfl_xor_sync(0xffffffffu, a1.z, 16);
    a1.w += __shfl_xor_sync(0xffffffffu, a1.w, 16);
    if (rel == 1) den += __shfl_xor_sync(0xffffffffu, den, 16);

    float sc;
    if (rel >= 2) sc = 1.0f / (float)(c < 1 ? 1 : c);
    else if (rel == 0) sc = (c > 0) ? rsqrtf((float)c) : 0.f;
    else sc = (c > 0) ? (1.0f / den) : 0.f;
    a0.x *= sc; a0.y *= sc; a0.z *= sc; a0.w *= sc;
    a1.x *= sc; a1.y *= sc; a1.z *= sc; a1.w *= sc;

    if (half == 0) {
        uint4 u;
        __half2 h;
        h = __floats2half2_rn(a0.x, a0.y); u.x = *reinterpret_cast<unsigned*>(&h);
        h = __floats2half2_rn(a0.z, a0.w); u.y = *reinterpret_cast<unsigned*>(&h);
        h = __floats2half2_rn(a1.x, a1.y); u.z = *reinterpret_cast<unsigned*>(&h);
        h = __floats2half2_rn(a1.z, a1.w); u.w = *reinterpret_cast<unsigned*>(&h);
        ((uint4*)g_feath[rel])[gw * 16 + q] = u;
    }
}

// ------------- fused tensor-core GEMM with register-prefetch pipeline ------------------
// BM=32, 256 threads (8 warps: 2 m-warps x 4 n-warps), grid 313 (2 blocks/SM).
// Stage A: 12 chunks (6 sources x two 64-K halves); LDG for chunk c+1 issued before
// computing chunk c from smem. Stage B: fp16 Rs @ Wout. Also restores deg_s invariant.
__global__ void __launch_bounds__(256) gemm_tc(const float* __restrict__ bout,
                                               float* __restrict__ out) {
    __shared__ __align__(16) char sbuf[27136];
    __half (*As)[APAD] = (__half (*)[APAD])sbuf;                       // 32x136x2 = 8704 B
    __half (*Bs)[APAD] = (__half (*)[APAD])(sbuf + 8704);              // 64x136x2 = 17408 B
    __half (*Rs)[APAD] = (__half (*)[APAD])sbuf;                       // alias As
    __half (*Ws2)[WPAD] = (__half (*)[WPAD])(sbuf + 8704);             // 128x72x2 = 18432 B

    int tid = threadIdx.x;
    int wid = tid >> 5, lane = tid & 31;
    int warp_m = wid & 1, warp_n = wid >> 1;   // 2 x 4
    int m0 = blockIdx.x * 32;
    int lrow = lane & 15, lcol = (lane >> 4) << 3;

    // restore deg_s zero-invariant (independent of this kernel's compute)
    for (int i = blockIdx.x * 256 + tid; i < N_CUST; i += gridDim.x * 256)
        g_deg_s[i] = 0;

    // per-thread load coordinates
    int am = tid >> 3, acc8 = tid & 7;         // A: row am (0..31), chunk col acc8
    int arow = m0 + am;

    float acc[4][4];
#pragma unroll
    for (int f = 0; f < 4; f++)
#pragma unroll
        for (int i = 0; i < 4; i++) acc[f][i] = 0.f;

    const uint4* Asrc[6] = {(const uint4*)g_feath[0], (const uint4*)g_feath[1],
                            (const uint4*)g_feath[2], (const uint4*)g_feath[3],
                            (const uint4*)g_feath[4], (const uint4*)g_xph};

    // ---- prologue: load chunk 0 into regs, commit to smem ----
    uint4 ra = make_uint4(0u, 0u, 0u, 0u);
    uint4 rb[4];
    {
        if (arow < N_PROD) ra = Asrc[0][arow * 16 + acc8];
        const uint4* Bp = (const uint4*)g_wh[0];
#pragma unroll
        for (int t = 0; t < 4; t++) {
            int idx = tid + t * 256;
            int k = idx >> 4, cc = idx & 15;
            rb[t] = Bp[k * 16 + cc];
        }
    }
    *(uint4*)&As[am][acc8 * 8] = ra;
#pragma unroll
    for (int t = 0; t < 4; t++) {
        int idx = tid + t * 256;
        int k = idx >> 4, cc = idx & 15;
        *(uint4*)&Bs[k][cc * 8] = rb[t];
    }
    __syncthreads();

    for (int c = 0; c < 12; c++) {
        // ---- prefetch chunk c+1 into registers (overlaps with compute below) ----
        if (c < 11) {
            int cn = c + 1;
            int pn = cn >> 1, hn = cn & 1;
            ra = make_uint4(0u, 0u, 0u, 0u);
            if (arow < N_PROD) ra = Asrc[pn][arow * 16 + hn * 8 + acc8];
            const uint4* Bp = (const uint4*)g_wh[pn];
#pragma unroll
            for (int t = 0; t < 4; t++) {
                int idx = tid + t * 256;
                int k = idx >> 4, cc = idx & 15;
                rb[t] = Bp[(hn * 64 + k) * 16 + cc];
            }
        }
        // ---- compute chunk c from smem ----
#pragma unroll
        for (int ks = 0; ks < 4; ks++) {
            int k0 = ks * 16;
            unsigned a[4];
            ldsm_x4(a[0], a[1], a[2], a[3],
                    smem_u32(&As[warp_m * 16 + lrow][k0 + lcol]));
#pragma unroll
            for (int j = 0; j < 2; j++) {
                unsigned bfrag[4];
                int nb = warp_n * 32 + j * 16;
                ldsm_x4t(bfrag[0], bfrag[1], bfrag[2], bfrag[3],
                         smem_u32(&Bs[k0 + lrow][nb + lcol]));
                mma16816(acc[j * 2], a, bfrag);
                mma16816(acc[j * 2 + 1], a, bfrag + 2);
            }
        }
        __syncthreads();
        if (c < 11) {
            *(uint4*)&As[am][acc8 * 8] = ra;
#pragma unroll
            for (int t = 0; t < 4; t++) {
                int idx = tid + t * 256;
                int k = idx >> 4, cc = idx & 15;
                *(uint4*)&Bs[k][cc * 8] = rb[t];
            }
        }
        __syncthreads();
    }

    // bias + relu -> Rs (fp16), load Wout -> Ws2
    {
        int r0 = warp_m * 16 + (lane >> 2);
#pragma unroll
        for (int f = 0; f < 4; f++) {
            int cc = warp_n * 32 + (f >> 1) * 16 + (f & 1) * 8 + (lane & 3) * 2;
            float2 bb = *(const float2*)&g_bias[cc];
            float v0 = acc[f][0] + bb.x; v0 = (v0 > 0.f) ? v0 : 0.f;
            float v1 = acc[f][1] + bb.y; v1 = (v1 > 0.f) ? v1 : 0.f;
            float v2 = acc[f][2] + bb.x; v2 = (v2 > 0.f) ? v2 : 0.f;
            float v3 = acc[f][3] + bb.y; v3 = (v3 > 0.f) ? v3 : 0.f;
            *(__half2*)&Rs[r0][cc] = __floats2half2_rn(v0, v1);
            *(__half2*)&Rs[r0 + 8][cc] = __floats2half2_rn(v2, v3);
        }
        const uint4* Wp = (const uint4*)g_wouth;
#pragma unroll
        for (int t = 0; t < 4; t++) {
            int idx = tid + t * 256;
            int k = idx >> 3, cc = idx & 7;
            *(uint4*)&Ws2[k][cc * 8] = Wp[k * 8 + cc];
        }
    }
    __syncthreads();

    float acc2[2][4];
#pragma unroll
    for (int f = 0; f < 2; f++)
#pragma unroll
        for (int i = 0; i < 4; i++) acc2[f][i] = 0.f;

#pragma unroll
    for (int ks = 0; ks < 8; ks++) {
        int k0 = ks * 16;
        unsigned a[4];
        ldsm_x4(a[0], a[1], a[2], a[3],
                smem_u32(&Rs[warp_m * 16 + lrow][k0 + lcol]));
        unsigned bfrag[4];
        int nb = warp_n * 16;
        ldsm_x4t(bfrag[0], bfrag[1], bfrag[2], bfrag[3],
                 smem_u32(&Ws2[k0 + lrow][nb + lcol]));
        mma16816(acc2[0], a, bfrag);
        mma16816(acc2[1], a, bfrag + 2);
    }

    // epilogue: + bout, store f32
    {
        int r = warp_m * 16 + (lane >> 2);
#pragma unroll
        for (int f = 0; f < 2; f++) {
            int cc = warp_n * 16 + f * 8 + (lane & 3) * 2;
            float2 bb = *(const float2*)&bout[cc];
            int row0 = m0 + r;
            int row1 = row0 + 8;
            if (row0 < N_PROD) {
                float2 v = make_float2(acc2[f][0] + bb.x, acc2[f][1] + bb.y);
                *(float2*)&out[row0 * 64 + cc] = v;
            }
            if (row1 < N_PROD) {
                float2 v = make_float2(acc2[f][2] + bb.x, acc2[f][3] + bb.y);
                *(float2*)&out[row1 * 64 + cc] = v;
            }
        }
    }
}

// ------------------------- launch -------------------------
extern "C" void kernel_launch(void* const* d_in, const int* in_sizes, int n_in,
                              void* d_out, int out_size) {
    const float* x_cust = (const float*)d_in[0];
    const float* x_prod = (const float*)d_in[1];
    EdgePtrs ep;
    for (int r = 0; r < NREL; r++) {
        ep.src[r] = (const int*)d_in[2 + 2 * r];
        ep.dst[r] = (const int*)d_in[3 + 2 * r];
    }
    ep.E = in_sizes[2];
    const float* W_gcn  = (const float*)d_in[12];
    const float* b_gcn  = (const float*)d_in[13];
    const float* Ws_gat = (const float*)d_in[14];
    const float* Wd_gat = (const float*)d_in[15];
    const float* a_s    = (const float*)d_in[16];
    const float* a_d    = (const float*)d_in[17];
    const float* b_gat  = (const float*)d_in[18];
    const float* Wl_to  = (const float*)d_in[19];
    const float* b_to   = (const float*)d_in[20];
    const float* Wr_to  = (const float*)d_in[21];
    const float* Wl_fr  = (const float*)d_in[22];
    const float* b_fr   = (const float*)d_in[23];
    const float* Wr_fr  = (const float*)d_in[24];
    const float* Wl_dv  = (const float*)d_in[25];
    const float* b_dv   = (const float*)d_in[26];
    const float* Wr_dv  = (const float*)d_in[27];
    const float* W_out  = (const float*)d_in[28];
    const float* b_out  = (const float*)d_in[29];

    setup_kernel<<<105, 256>>>(Ws_gat, Wd_gat, a_s, a_d,
                               b_gcn, b_gat, b_to, b_fr, b_dv,
                               W_gcn, Wl_to, Wl_fr, Wl_dv,
                               Wr_to, Wr_fr, Wr_dv, W_out);
    phase1_kernel<<<PHASE1_EDGE_BLOCKS + ROWDOT_BLOCKS, 256>>>(x_cust, x_prod, ep);

    dim3 agrid((N_PROD + 7) / 8, 5);
    agg_all<<<agrid, 256>>>();

    gemm_tc<<<(N_PROD + 31) / 32, 256>>>(b_out, (float*)d_out);
}

// round 13
// speedup vs baseline: 1.6392x; 1.6183x over previous
#include <cuda_runtime.h>
#include <cuda_fp16.h>

#define N_CUST 100000
#define N_PROD 10000
#define NREL 5
#define SEG 128                 // fixed CSR segment stride (max degree ~80, 11 sigma margin)
#define ROWDOT_BLOCKS 13750     // (N_CUST+N_PROD) warps / 8
#define SCAT_BLOCKS_PER 160
#define PHASE1_EDGE_BLOCKS (SCAT_BLOCKS_PER * 5)
#define APAD 136                // halves per smem row (272B stride; 272 mod 128 = 16 -> conflict-free)
#define WPAD 72                 // halves per smem row for Wout tile (144B stride)

// ------------------------- device scratch (no allocs allowed) -------------------------
__device__ float  g_wsvec[128];           // Ws_gat @ a_s
__device__ float  g_wdvec[128];           // Wd_gat @ a_d
__device__ float  g_bias[128];            // sum of 5 branch biases
__device__ float  g_ls[N_CUST];
__device__ float  g_ld[N_PROD];
__device__ int    g_deg_s[N_CUST];        // purchase src degree
__device__ int    g_cnt[NREL][N_PROD];    // cursor during scatter == degree after
__device__ int    g_sorted[NREL][N_PROD * SEG];
__device__ uint2  g_xch[N_CUST * 32];     // x_cust rows as fp16 (32 x 8B per row)
__device__ uint2  g_xph[N_PROD * 32];     // x_prod rows as fp16
__device__ uint2  g_feath[NREL][N_PROD * 32];  // aggregated features, fp16
__device__ __half g_wh[6][128 * 128];     // fp16 weights: Wg,Wsg,Wlt,Wlf,Wld,wrsum
__device__ __half g_wouth[128 * 64];      // fp16 W_out

struct EdgePtrs {
    const int* src[NREL];
    const int* dst[NREL];
    int E;
};

// ------------------------- tensor-core helpers -------------------------
__device__ __forceinline__ unsigned smem_u32(const void* p) {
    return (unsigned)__cvta_generic_to_shared(p);
}
__device__ __forceinline__ void ldsm_x4(unsigned& r0, unsigned& r1, unsigned& r2, unsigned& r3,
                                        unsigned addr) {
    asm volatile("ldmatrix.sync.aligned.m8n8.x4.shared.b16 {%0,%1,%2,%3}, [%4];"
                 : "=r"(r0), "=r"(r1), "=r"(r2), "=r"(r3) : "r"(addr));
}
__device__ __forceinline__ void ldsm_x4t(unsigned& r0, unsigned& r1, unsigned& r2, unsigned& r3,
                                         unsigned addr) {
    asm volatile("ldmatrix.sync.aligned.m8n8.x4.trans.shared.b16 {%0,%1,%2,%3}, [%4];"
                 : "=r"(r0), "=r"(r1), "=r"(r2), "=r"(r3) : "r"(addr));
}
__device__ __forceinline__ void mma16816(float* d, const unsigned* a, const unsigned* b) {
    asm volatile(
        "mma.sync.aligned.m16n8k16.row.col.f32.f16.f16.f32 "
        "{%0,%1,%2,%3},{%4,%5,%6,%7},{%8,%9},{%0,%1,%2,%3};"
        : "+f"(d[0]), "+f"(d[1]), "+f"(d[2]), "+f"(d[3])
        : "r"(a[0]), "r"(a[1]), "r"(a[2]), "r"(a[3]), "r"(b[0]), "r"(b[1]));
}

// ------------------------- setup: prep + fp16 weight conversion + zero ----------------
__global__ void setup_kernel(const float* __restrict__ Ws, const float* __restrict__ Wd,
                             const float* __restrict__ a_s, const float* __restrict__ a_d,
                             const float* __restrict__ bg, const float* __restrict__ bgat,
                             const float* __restrict__ bto, const float* __restrict__ bfrom,
                             const float* __restrict__ bdiv,
                             const float* __restrict__ Wg, const float* __restrict__ Wlt,
                             const float* __restrict__ Wlf, const float* __restrict__ Wld,
                             const float* __restrict__ Wrt, const float* __restrict__ Wrf,
                             const float* __restrict__ Wrd, const float* __restrict__ Wout) {
    int b = blockIdx.x;
    int tid = threadIdx.x;
    if (b == 0) {
        if (tid < 128) {
            float s1 = 0.f, s2 = 0.f;
            for (int j = 0; j < 128; j++) {
                s1 += Ws[tid * 128 + j] * a_s[j];
                s2 += Wd[tid * 128 + j] * a_d[j];
            }
            g_wsvec[tid] = s1;
            g_wdvec[tid] = s2;
            g_bias[tid] = bg[tid] + bgat[tid] + bto[tid] + bfrom[tid] + bdiv[tid];
        }
    } else if (b <= 96) {
        int p = (b - 1) >> 4;
        int idx = ((b - 1) & 15) * 1024 + tid * 4;
        const float* srcs[5] = {Wg, Ws, Wlt, Wlf, Wld};
        float4 v;
        if (p < 5) v = *(const float4*)&srcs[p][idx];
        else {
            float4 v0 = *(const float4*)&Wrt[idx];
            float4 v1 = *(const float4*)&Wrf[idx];
            float4 v2 = *(const float4*)&Wrd[idx];
            v = make_float4(v0.x + v1.x + v2.x, v0.y + v1.y + v2.y,
                            v0.z + v1.z + v2.z, v0.w + v1.w + v2.w);
        }
        __half2 h0 = __floats2half2_rn(v.x, v.y);
        __half2 h1 = __floats2half2_rn(v.z, v.w);
        uint2 u;
        u.x = *reinterpret_cast<unsigned*>(&h0);
        u.y = *reinterpret_cast<unsigned*>(&h1);
        *(uint2*)&g_wh[p][idx] = u;
    } else if (b <= 104) {
        int idx = (b - 97) * 1024 + tid * 4;
        float4 v = *(const float4*)&Wout[idx];
        __half2 h0 = __floats2half2_rn(v.x, v.y);
        __half2 h1 = __floats2half2_rn(v.z, v.w);
        uint2 u;
        u.x = *reinterpret_cast<unsigned*>(&h0);
        u.y = *reinterpret_cast<unsigned*>(&h1);
        *(uint2*)&g_wouth[idx] = u;
    } else {
        int n = N_CUST + NREL * N_PROD;
        int stride = (gridDim.x - 105) * 256;
        for (int i = (b - 105) * 256 + tid; i < n; i += stride) {
            if (i < N_CUST) g_deg_s[i] = 0;
            else ((int*)g_cnt)[i - N_CUST] = 0;
        }
    }
}

// ---- phase1: fused {5x direct scatter (slice 0 also builds deg_s), rowdot/convert} ---
__global__ void phase1_kernel(const float* __restrict__ xc, const float* __restrict__ xp,
                              EdgePtrs ep) {
    int b = blockIdx.x;
    if (b < PHASE1_EDGE_BLOCKS) {
        int slice = b / SCAT_BLOCKS_PER;   // relation 0..4
        int bx = b % SCAT_BLOCKS_PER;
        const int* src = ep.src[slice];
        const int* dst = ep.dst[slice];
        int* cnt = g_cnt[slice];
        int* srt = g_sorted[slice];
        if (slice == 0) {
            for (int i = bx * 256 + (int)threadIdx.x; i < ep.E; i += SCAT_BLOCKS_PER * 256) {
                int s = src[i];
                int d = dst[i];
                atomicAdd(&g_deg_s[s], 1);
                int p = atomicAdd(&cnt[d], 1);
                if (p < SEG) srt[(d << 7) + p] = s;
            }
        } else {
            for (int i = bx * 256 + (int)threadIdx.x; i < ep.E; i += SCAT_BLOCKS_PER * 256) {
                int d = dst[i];
                int p = atomicAdd(&cnt[d], 1);
                if (p < SEG) srt[(d << 7) + p] = src[i];
            }
        }
    } else {
        int b2 = b - PHASE1_EDGE_BLOCKS;
        int gw = (b2 * 256 + (int)threadIdx.x) >> 5;
        int lane = threadIdx.x & 31;
        float4 wv, xv;
        if (gw < N_CUST) {
            wv = ((const float4*)g_wsvec)[lane];
            xv = ((const float4*)xc)[gw * 32 + lane];
        } else {
            wv = ((const float4*)g_wdvec)[lane];
            xv = ((const float4*)xp)[(gw - N_CUST) * 32 + lane];
        }
        __half2 h0 = __floats2half2_rn(xv.x, xv.y);
        __half2 h1 = __floats2half2_rn(xv.z, xv.w);
        uint2 u;
        u.x = *reinterpret_cast<unsigned*>(&h0);
        u.y = *reinterpret_cast<unsigned*>(&h1);
        if (gw < N_CUST) g_xch[gw * 32 + lane] = u;
        else g_xph[(gw - N_CUST) * 32 + lane] = u;
        float d = xv.x * wv.x + xv.y * wv.y + xv.z * wv.z + xv.w * wv.w;
#pragma unroll
        for (int o = 16; o; o >>= 1) d += __shfl_xor_sync(0xffffffffu, d, o);
        if (lane == 0) {
            if (gw < N_CUST) g_ls[gw] = d; else g_ld[gw - N_CUST] = d;
        }
    }
}

// ------------------------- fp16 gather helper (uint4 = 8 halves) ----------------------
__device__ __forceinline__ void acc_h4(float4& a0, float4& a1, uint4 u, float w) {
    __half2* h = reinterpret_cast<__half2*>(&u);
    float2 f0 = __half22float2(h[0]);
    float2 f1 = __half22float2(h[1]);
    float2 f2 = __half22float2(h[2]);
    float2 f3 = __half22float2(h[3]);
    a0.x += w * f0.x; a0.y += w * f0.y; a0.z += w * f1.x; a0.w += w * f1.y;
    a1.x += w * f2.x; a1.y += w * f2.y; a1.z += w * f3.x; a1.w += w * f3.y;
}

// ------------------------- all 5 aggregations: warp = dst row, 4 edges in flight ------
// 16 lanes cover the 256B fp16 row (uint4 each); half = lane>>4 picks edge parity.
__global__ void agg_all() {
    int gw = (blockIdx.x * blockDim.x + threadIdx.x) >> 5;
    if (gw >= N_PROD) return;
    int lane = threadIdx.x & 31;
    int half = lane >> 4;       // edge parity
    int q = lane & 15;          // 16B chunk within row
    int rel = blockIdx.y;
    int c = g_cnt[rel][gw];
    if (c > SEG) c = SEG;
    const int* srt = &g_sorted[rel][gw << 7];
    const uint4* xh4 = (const uint4*)g_xch;
    float4 a0 = make_float4(0.f, 0.f, 0.f, 0.f);
    float4 a1 = make_float4(0.f, 0.f, 0.f, 0.f);
    float den = 0.f;
    float ldv = (rel == 1) ? g_ld[gw] : 0.f;

    int e = half;
    // 4 edges in flight per half-warp (8 independent LDG.128 per warp iteration)
    for (; e + 6 < c; e += 8) {
        int s0 = srt[e], s1 = srt[e + 2], s2 = srt[e + 4], s3 = srt[e + 6];
        float w0, w1, w2, w3;
        if (rel >= 2) { w0 = w1 = w2 = w3 = 1.f; }
        else if (rel == 0) {
            w0 = rsqrtf((float)g_deg_s[s0]);
            w1 = rsqrtf((float)g_deg_s[s1]);
            w2 = rsqrtf((float)g_deg_s[s2]);
            w3 = rsqrtf((float)g_deg_s[s3]);
        } else {
            float l0 = g_ls[s0] + ldv;
            float l1 = g_ls[s1] + ldv;
            float l2 = g_ls[s2] + ldv;
            float l3 = g_ls[s3] + ldv;
            l0 = (l0 > 0.f) ? l0 : 0.2f * l0;
            l1 = (l1 > 0.f) ? l1 : 0.2f * l1;
            l2 = (l2 > 0.f) ? l2 : 0.2f * l2;
            l3 = (l3 > 0.f) ? l3 : 0.2f * l3;
            w0 = __expf(l0); w1 = __expf(l1); w2 = __expf(l2); w3 = __expf(l3);
            den += (w0 + w1) + (w2 + w3);
        }
        uint4 u0 = xh4[s0 * 16 + q];
        uint4 u1 = xh4[s1 * 16 + q];
        uint4 u2 = xh4[s2 * 16 + q];
        uint4 u3 = xh4[s3 * 16 + q];
        acc_h4(a0, a1, u0, w0);
        acc_h4(a0, a1, u1, w1);
        acc_h4(a0, a1, u2, w2);
        acc_h4(a0, a1, u3, w3);
    }
    for (; e < c; e += 2) {
        int s0 = srt[e];
        float w0;
        if (rel >= 2) w0 = 1.f;
        else if (rel == 0) w0 = rsqrtf((float)g_deg_s[s0]);
        else {
            float l0 = g_ls[s0] + ldv;
            l0 = (l0 > 0.f) ? l0 : 0.2f * l0;
            w0 = __expf(l0);
            den += w0;
        }
        uint4 u0 = xh4[s0 * 16 + q];
        acc_h4(a0, a1, u0, w0);
    }

    // combine the two edge-parity halves
    a0.x += __shfl_xor_sync(0xffffffffu, a0.x, 16);
    a0.y += __shfl_xor_sync(0xffffffffu, a0.y, 16);
    a0.z += __shfl_xor_sync(0xffffffffu, a0.z, 16);
    a0.w += __shfl_xor_sync(0xffffffffu, a0.w, 16);
    a1.x += __shfl_xor_sync(0xffffffffu, a1.x, 16);
    a1.y += __shfl_xor_sync(0xffffffffu, a1.y, 16);
    a1.z += __shfl_xor_sync(0xffffffffu, a1.z, 16);
    a1.w += __shfl_xor_sync(0xffffffffu, a1.w, 16);
    if (rel == 1) den += __shfl_xor_sync(0xffffffffu, den, 16);

    float sc;
    if (rel >= 2) sc = 1.0f / (float)(c < 1 ? 1 : c);
    else if (rel == 0) sc = (c > 0) ? rsqrtf((float)c) : 0.f;
    else sc = (c > 0) ? (1.0f / den) : 0.f;
    a0.x *= sc; a0.y *= sc; a0.z *= sc; a0.w *= sc;
    a1.x *= sc; a1.y *= sc; a1.z *= sc; a1.w *= sc;

    if (half == 0) {
        uint4 u;
        __half2 h;
        h = __floats2half2_rn(a0.x, a0.y); u.x = *reinterpret_cast<unsigned*>(&h);
        h = __floats2half2_rn(a0.z, a0.w); u.y = *reinterpret_cast<unsigned*>(&h);
        h = __floats2half2_rn(a1.x, a1.y); u.z = *reinterpret_cast<unsigned*>(&h);
        h = __floats2half2_rn(a1.z, a1.w); u.w = *reinterpret_cast<unsigned*>(&h);
        ((uint4*)g_feath[rel])[gw * 16 + q] = u;
    }
}

// ------------- fused tensor-core GEMM with register-prefetch pipeline ------------------
// BM=32, 256 threads (8 warps: 2 m-warps x 4 n-warps), grid 313 (2 blocks/SM).
// Stage A: 12 chunks (6 sources x two 64-K halves); LDG for chunk c+1 issued before
// computing chunk c from smem. Stage B: fp16 Rs @ Wout.
__global__ void __launch_bounds__(256) gemm_tc(const float* __restrict__ bout,
                                               float* __restrict__ out) {
    __shared__ __align__(16) char sbuf[27136];
    __half (*As)[APAD] = (__half (*)[APAD])sbuf;                       // 32x136x2 = 8704 B
    __half (*Bs)[APAD] = (__half (*)[APAD])(sbuf + 8704);              // 64x136x2 = 17408 B
    __half (*Rs)[APAD] = (__half (*)[APAD])sbuf;                       // alias As
    __half (*Ws2)[WPAD] = (__half (*)[WPAD])(sbuf + 8704);             // 128x72x2 = 18432 B

    int tid = threadIdx.x;
    int wid = tid >> 5, lane = tid & 31;
    int warp_m = wid & 1, warp_n = wid >> 1;   // 2 x 4
    int m0 = blockIdx.x * 32;
    int lrow = lane & 15, lcol = (lane >> 4) << 3;

    // per-thread load coordinates
    int am = tid >> 3, acc8 = tid & 7;         // A: row am (0..31), chunk col acc8
    int arow = m0 + am;

    float acc[4][4];
#pragma unroll
    for (int f = 0; f < 4; f++)
#pragma unroll
        for (int i = 0; i < 4; i++) acc[f][i] = 0.f;

    const uint4* Asrc[6] = {(const uint4*)g_feath[0], (const uint4*)g_feath[1],
                            (const uint4*)g_feath[2], (const uint4*)g_feath[3],
                            (const uint4*)g_feath[4], (const uint4*)g_xph};

    // ---- prologue: load chunk 0 into regs, commit to smem ----
    uint4 ra = make_uint4(0u, 0u, 0u, 0u);
    uint4 rb[4];
    {
        if (arow < N_PROD) ra = Asrc[0][arow * 16 + acc8];
        const uint4* Bp = (const uint4*)g_wh[0];
#pragma unroll
        for (int t = 0; t < 4; t++) {
            int idx = tid + t * 256;
            int k = idx >> 4, cc = idx & 15;
            rb[t] = Bp[k * 16 + cc];
        }
    }
    *(uint4*)&As[am][acc8 * 8] = ra;
#pragma unroll
    for (int t = 0; t < 4; t++) {
        int idx = tid + t * 256;
        int k = idx >> 4, cc = idx & 15;
        *(uint4*)&Bs[k][cc * 8] = rb[t];
    }
    __syncthreads();

    for (int c = 0; c < 12; c++) {
        // ---- prefetch chunk c+1 into registers (overlaps with compute below) ----
        if (c < 11) {
            int cn = c + 1;
            int pn = cn >> 1, hn = cn & 1;
            ra = make_uint4(0u, 0u, 0u, 0u);
            if (arow < N_PROD) ra = Asrc[pn][arow * 16 + hn * 8 + acc8];
            const uint4* Bp = (const uint4*)g_wh[pn];
#pragma unroll
            for (int t = 0; t < 4; t++) {
                int idx = tid + t * 256;
                int k = idx >> 4, cc = idx & 15;
                rb[t] = Bp[(hn * 64 + k) * 16 + cc];
            }
        }
        // ---- compute chunk c from smem ----
#pragma unroll
        for (int ks = 0; ks < 4; ks++) {
            int k0 = ks * 16;
            unsigned a[4];
            ldsm_x4(a[0], a[1], a[2], a[3],
                    smem_u32(&As[warp_m * 16 + lrow][k0 + lcol]));
#pragma unroll
            for (int j = 0; j < 2; j++) {
                unsigned bfrag[4];
                int nb = warp_n * 32 + j * 16;
                ldsm_x4t(bfrag[0], bfrag[1], bfrag[2], bfrag[3],
                         smem_u32(&Bs[k0 + lrow][nb + lcol]));
                mma16816(acc[j * 2], a, bfrag);
                mma16816(acc[j * 2 + 1], a, bfrag + 2);
            }
        }
        __syncthreads();
        if (c < 11) {
            *(uint4*)&As[am][acc8 * 8] = ra;
#pragma unroll
            for (int t = 0; t < 4; t++) {
                int idx = tid + t * 256;
                int k = idx >> 4, cc = idx & 15;
                *(uint4*)&Bs[k][cc * 8] = rb[t];
            }
        }
        __syncthreads();
    }

    // bias + relu -> Rs (fp16), load Wout -> Ws2
    {
        int r0 = warp_m * 16 + (lane >> 2);
#pragma unroll
        for (int f = 0; f < 4; f++) {
            int cc = warp_n * 32 + (f >> 1) * 16 + (f & 1) * 8 + (lane & 3) * 2;
            float2 bb = *(const float2*)&g_bias[cc];
            float v0 = acc[f][0] + bb.x; v0 = (v0 > 0.f) ? v0 : 0.f;
            float v1 = acc[f][1] + bb.y; v1 = (v1 > 0.f) ? v1 : 0.f;
            float v2 = acc[f][2] + bb.x; v2 = (v2 > 0.f) ? v2 : 0.f;
            float v3 = acc[f][3] + bb.y; v3 = (v3 > 0.f) ? v3 : 0.f;
            *(__half2*)&Rs[r0][cc] = __floats2half2_rn(v0, v1);
            *(__half2*)&Rs[r0 + 8][cc] = __floats2half2_rn(v2, v3);
        }
        const uint4* Wp = (const uint4*)g_wouth;
#pragma unroll
        for (int t = 0; t < 4; t++) {
            int idx = tid + t * 256;
            int k = idx >> 3, cc = idx & 7;
            *(uint4*)&Ws2[k][cc * 8] = Wp[k * 8 + cc];
        }
    }
    __syncthreads();

    float acc2[2][4];
#pragma unroll
    for (int f = 0; f < 2; f++)
#pragma unroll
        for (int i = 0; i < 4; i++) acc2[f][i] = 0.f;

#pragma unroll
    for (int ks = 0; ks < 8; ks++) {
        int k0 = ks * 16;
        unsigned a[4];
        ldsm_x4(a[0], a[1], a[2], a[3],
                smem_u32(&Rs[warp_m * 16 + lrow][k0 + lcol]));
        unsigned bfrag[4];
        int nb = warp_n * 16;
        ldsm_x4t(bfrag[0], bfrag[1], bfrag[2], bfrag[3],
                 smem_u32(&Ws2[k0 + lrow][nb + lcol]));
        mma16816(acc2[0], a, bfrag);
        mma16816(acc2[1], a, bfrag + 2);
    }

    // epilogue: + bout, store f32
    {
        int r = warp_m * 16 + (lane >> 2);
#pragma unroll
        for (int f = 0; f < 2; f++) {
            int cc = warp_n * 16 + f * 8 + (lane & 3) * 2;
            float2 bb = *(const float2*)&bout[cc];
            int row0 = m0 + r;
            int row1 = row0 + 8;
            if (row0 < N_PROD) {
                float2 v = make_float2(acc2[f][0] + bb.x, acc2[f][1] + bb.y);
                *(float2*)&out[row0 * 64 + cc] = v;
            }
            if (row1 < N_PROD) {
                float2 v = make_float2(acc2[f][2] + bb.x, acc2[f][3] + bb.y);
                *(float2*)&out[row1 * 64 + cc] = v;
            }
        }
    }
}

// ------------------------- launch -------------------------
extern "C" void kernel_launch(void* const* d_in, const int* in_sizes, int n_in,
                              void* d_out, int out_size) {
    const float* x_cust = (const float*)d_in[0];
    const float* x_prod = (const float*)d_in[1];
    EdgePtrs ep;
    for (int r = 0; r < NREL; r++) {
        ep.src[r] = (const int*)d_in[2 + 2 * r];
        ep.dst[r] = (const int*)d_in[3 + 2 * r];
    }
    ep.E = in_sizes[2];
    const float* W_gcn  = (const float*)d_in[12];
    const float* b_gcn  = (const float*)d_in[13];
    const float* Ws_gat = (const float*)d_in[14];
    const float* Wd_gat = (const float*)d_in[15];
    const float* a_s    = (const float*)d_in[16];
    const float* a_d    = (const float*)d_in[17];
    const float* b_gat  = (const float*)d_in[18];
    const float* Wl_to  = (const float*)d_in[19];
    const float* b_to   = (const float*)d_in[20];
    const float* Wr_to  = (const float*)d_in[21];
    const float* Wl_fr  = (const float*)d_in[22];
    const float* b_fr   = (const float*)d_in[23];
    const float* Wr_fr  = (const float*)d_in[24];
    const float* Wl_dv  = (const float*)d_in[25];
    const float* b_dv   = (const float*)d_in[26];
    const float* Wr_dv  = (const float*)d_in[27];
    const float* W_out  = (const float*)d_in[28];
    const float* b_out  = (const float*)d_in[29];

    setup_kernel<<<321, 256>>>(Ws_gat, Wd_gat, a_s, a_d,
                               b_gcn, b_gat, b_to, b_fr, b_dv,
                               W_gcn, Wl_to, Wl_fr, Wl_dv,
                               Wr_to, Wr_fr, Wr_dv, W_out);
    phase1_kernel<<<PHASE1_EDGE_BLOCKS + ROWDOT_BLOCKS, 256>>>(x_cust, x_prod, ep);

    dim3 agrid((N_PROD + 7) / 8, 5);
    agg_all<<<agrid, 256>>>();

    gemm_tc<<<(N_PROD + 31) / 32, 256>>>(b_out, (float*)d_out);
}